// round 16
// baseline (speedup 1.0000x reference)
#include <cuda_runtime.h>
#include <cuda_fp16.h>
#include <cstdint>
#include <math.h>

#define FULLMASK 0xffffffffu
#define LDXH 264   // X/H row stride (halfs) >= 256; word-stride 132 % 32 == 4 -> conflict-free

// ==================== device scratch (no allocations allowed) ===============
__device__ int      g_idx[4 * 4096 * 32];
__device__ float    g_abs[4 * 4096 * 96];
__device__ unsigned g_pooled[4 * 256];
__device__ float4   g_w1t[6 * 1024];     // 6 chunks x 16KB fp16 slice-major images
__device__ float4   g_w2t[8 * 1024];     // 8 chunks x 16KB
__device__ float    g_fp1[16 * 1024], g_fp2[16 * 1024], g_ft[1024];

// ==================== helpers ===============================================
__device__ __forceinline__ uint32_t smem_u32(const void* p) {
    uint32_t a;
    asm("{ .reg .u64 t; cvta.to.shared.u64 t, %1; cvt.u32.u64 %0, t; }" : "=r"(a) : "l"(p));
    return a;
}
__device__ __forceinline__ uint16_t h16(float x) {
    uint16_t u;
    asm("cvt.rn.f16.f32 %0, %1;" : "=h"(u) : "f"(x));
    return u;
}
__device__ __forceinline__ uint32_t hpack(float a, float b) {
    return (uint32_t)h16(a) | ((uint32_t)h16(b) << 16);
}
__device__ __forceinline__ unsigned fkey(float f) {
    int i = __float_as_int(f);
    return (i >= 0) ? ((unsigned)i | 0x80000000u) : ~(unsigned)i;
}
__device__ __forceinline__ float funkey(unsigned u) {
    int i = (u & 0x80000000u) ? (int)(u & 0x7fffffffu) : (int)(~u);
    return __int_as_float(i);
}
__device__ __forceinline__ float gelu_exact(float x) {
    return 0.5f * x * (1.0f + erff(x * 0.70710678118654752f));
}
// m16n8k16 fp16 warp MMA, fp32 accumulate (family-portable sm_80+)
__device__ __forceinline__ void mma16(float4& d, uint32_t a0, uint32_t a1,
                                      uint32_t a2, uint32_t a3, uint32_t b0, uint32_t b1) {
    asm volatile("mma.sync.aligned.m16n8k16.row.col.f32.f16.f16.f32 "
                 "{%0,%1,%2,%3}, {%4,%5,%6,%7}, {%8,%9}, {%0,%1,%2,%3};"
                 : "+f"(d.x), "+f"(d.y), "+f"(d.z), "+f"(d.w)
                 : "r"(a0), "r"(a1), "r"(a2), "r"(a3), "r"(b0), "r"(b1));
}
__device__ __forceinline__ void cp16(uint32_t sdst, const void* gsrc) {
    asm volatile("cp.async.cg.shared.global [%0], [%1], 16;" :: "r"(sdst), "l"(gsrc));
}
__device__ __forceinline__ void bar_pair(int id) {
    asm volatile("bar.sync %0, 64;" :: "r"(id) : "memory");
}

// ==================== kernel 0: init pooled =================================
__global__ void k_init() {
    int t = blockIdx.x * blockDim.x + threadIdx.x;
    if (t < 1024) g_pooled[t] = 0x007FFFFFu;   // fkey(-inf)
}

// ==================== kernel P: fp16 slice-major fragment weight images =====
// chunk(16KB) = 4 wc-slices of 4KB; slice = [ks(2)][nt8(8)][lane(32)] uint2
// uint2 = {half2(W[k0][n],W[k0+1][n]), half2(W[k0+8][n],W[k0+9][n])}
//   k0 = c*32 + ks*16 + 2*(lane&3),  n = wc*64 + nt8*8 + lane/4
__global__ __launch_bounds__(256) void k_prep(const float* __restrict__ w1,
                                              const float* __restrict__ w2) {
    int id = blockIdx.x * 256 + threadIdx.x;
    if (id < 12288) {                      // layer 1: 6 chunks
        int c = id >> 11, rem = id & 2047;
        int wc = rem >> 9, rem2 = rem & 511;
        int ks = rem2 >> 8, rem3 = rem2 & 255;
        int nt8 = rem3 >> 5, lane = rem3 & 31;
        int k0 = c * 32 + ks * 16 + 2 * (lane & 3);
        int n = wc * 64 + nt8 * 8 + (lane >> 2);
        float v0 = (k0     < 187) ? w1[(k0    ) * 256 + n] : 0.f;
        float v1 = (k0 + 1 < 187) ? w1[(k0 + 1) * 256 + n] : 0.f;
        float v2 = (k0 + 8 < 187) ? w1[(k0 + 8) * 256 + n] : 0.f;
        float v3 = (k0 + 9 < 187) ? w1[(k0 + 9) * 256 + n] : 0.f;
        uint2 r; r.x = hpack(v0, v1); r.y = hpack(v2, v3);
        ((uint2*)g_w1t)[id] = r;
    } else if (id < 12288 + 16384) {       // layer 2: 8 chunks
        int e = id - 12288;
        int c = e >> 11, rem = e & 2047;
        int wc = rem >> 9, rem2 = rem & 511;
        int ks = rem2 >> 8, rem3 = rem2 & 255;
        int nt8 = rem3 >> 5, lane = rem3 & 31;
        int k0 = c * 32 + ks * 16 + 2 * (lane & 3);
        int n = wc * 64 + nt8 * 8 + (lane >> 2);
        uint2 r;
        r.x = hpack(w2[k0 * 256 + n], w2[(k0 + 1) * 256 + n]);
        r.y = hpack(w2[(k0 + 8) * 256 + n], w2[(k0 + 9) * 256 + n]);
        ((uint2*)g_w2t)[e] = r;
    }
}

// ==================== kernel 1: ball query + absolute emb (validated) =======
__global__ __launch_bounds__(256) void k_ball(const float* __restrict__ xyz) {
    __shared__ float sx[4096], sy[4096], sz[4096];
    const int b = blockIdx.y;
    const float* base = xyz + (size_t)b * 4096 * 3;
    for (int i = threadIdx.x; i < 4096; i += 256) {
        float3 v = *(const float3*)(base + 3 * i);
        sx[i] = v.x; sy[i] = v.y; sz[i] = v.z;
    }
    __syncthreads();
    const int lane = threadIdx.x & 31, warp = threadIdx.x >> 5;
    const int n = blockIdx.x * 8 + warp;
    const float qx = sx[n], qy = sy[n], qz = sz[n];
    const int p = (b << 12) + n;
    int cnt = 0, fm = n;
    for (int c = 0; c < 128; c++) {
        int m = c * 32 + lane;
        float dx = sx[m] - qx, dy = sy[m] - qy, dz = sz[m] - qz;
        float sq = __fadd_rn(__fadd_rn(__fmul_rn(dx, dx), __fmul_rn(dy, dy)), __fmul_rn(dz, dz));
        bool in = (sq <= 0.0256f);
        unsigned mask = __ballot_sync(FULLMASK, in);
        if (mask) {
            if (cnt == 0) fm = c * 32 + (__ffs(mask) - 1);
            if (in) {
                int pos = cnt + __popc(mask & ((1u << lane) - 1u));
                if (pos < 32) g_idx[p * 32 + pos] = m;
            }
            cnt += __popc(mask);
            if (cnt >= 32) break;
        }
    }
    for (int k = cnt + lane; k < 32; k += 32) g_idx[p * 32 + k] = fm;
    int jj = lane & 15;
    float fr = expf((-logf(10000.0f) * (float)jj) / 15.0f);
    float co[3] = {qx, qy, qz};
#pragma unroll
    for (int a = 0; a < 3; a++) {
        float ang = co[a] * fr;
        g_abs[(size_t)p * 96 + a * 32 + lane] = (lane >= 16) ? cosf(ang) : sinf(ang);
    }
}

// ==================== kernel 2: fp16 mma.sync fused MLP + joint max =========
// CTA: 64 rows x 256 cols; 256 threads, 8 warps in 2(M) x 4(N) grid.
// 2 CTAs/SM; per-wc-pair weight slices + named barriers; 3-stage cp.async pipe.
#define SMEM_DYN (64 * LDXH * 2 + 3 * 16384)

// fully-unrolled 3-stage-pipelined 32-kcol-chunk GEMM (fp16 fragments).
// Invariant on entry: chunk 0 and chunk 1 slices committed (2 groups in flight).
// Buffer for chunk i is i%3 (layer-2 global offset 6 == 0 mod 3, so consistent).
template <int NCH, bool PRELOAD>
__device__ __forceinline__ void gemm_loop(const __half* Xh,
                                          char* Wb, const float4* gw,
                                          const float4* next_gw,
                                          int wr, int wc, int lane, int pidx,
                                          float4 acc[2][8]) {
    const int gid = lane >> 2, tid4 = lane & 3;
    const uint32_t wbase = smem_u32(Wb) + wc * 4096;
    const __half* Ar = Xh + (wr * 32 + gid) * LDXH + 2 * tid4;
#pragma unroll
    for (int i = 0; i < NCH; i++) {
        // chunk i must be complete: with PRELOAD every iter commits one group,
        // so exactly one newer group may remain. Without PRELOAD the last iter
        // has no newer commit -> full drain.
        if (!PRELOAD && i == NCH - 1) {
            asm volatile("cp.async.wait_group 0;" ::: "memory");
        } else {
            asm volatile("cp.async.wait_group 1;" ::: "memory");
        }
        bar_pair(wc + 1);
        {   // commit load for chunk i+2 (own wc slice)
            const int nxt = i + 2;
            uint32_t dst = wbase + (uint32_t)((nxt % 3) * 16384);
            if (nxt < NCH) {
                const float4* src = gw + nxt * 1024 + wc * 256;
#pragma unroll
                for (int u = 0; u < 4; u++) cp16(dst + (pidx + u * 64) * 16, src + pidx + u * 64);
                asm volatile("cp.async.commit_group;" ::: "memory");
            } else if (PRELOAD) {
                const float4* src = next_gw + (nxt - NCH) * 1024 + wc * 256;
#pragma unroll
                for (int u = 0; u < 4; u++) cp16(dst + (pidx + u * 64) * 16, src + pidx + u * 64);
                asm volatile("cp.async.commit_group;" ::: "memory");
            }
        }
        const uint2* Bslice = (const uint2*)(Wb + (i % 3) * 16384 + wc * 4096);
#pragma unroll
        for (int ks = 0; ks < 2; ks++) {
            const int kbase = i * 32 + ks * 16;     // compile-time
            uint32_t a[2][4];
#pragma unroll
            for (int tile = 0; tile < 2; tile++) {
                const __half* At = Ar + tile * 16 * LDXH + kbase;
                a[tile][0] = *(const uint32_t*)(At);
                a[tile][1] = *(const uint32_t*)(At + 8 * LDXH);
                a[tile][2] = *(const uint32_t*)(At + 8);
                a[tile][3] = *(const uint32_t*)(At + 8 * LDXH + 8);
            }
            uint2 b[8];
            const uint2* Bp = Bslice + ks * 256 + lane;
#pragma unroll
            for (int nt = 0; nt < 8; nt++) b[nt] = Bp[nt * 32];
#pragma unroll
            for (int tile = 0; tile < 2; tile++)
#pragma unroll
                for (int nt = 0; nt < 8; nt++)
                    mma16(acc[tile][nt], a[tile][0], a[tile][1], a[tile][2], a[tile][3],
                          b[nt].x, b[nt].y);
        }
    }
    __syncthreads();
}

__global__ __launch_bounds__(256, 2) void k_mlp(
    const float* __restrict__ xyz, const float* __restrict__ pf,
    const float* __restrict__ b1, const float* __restrict__ g1, const float* __restrict__ be1,
    const float* __restrict__ b2, const float* __restrict__ g2, const float* __restrict__ be2) {
    extern __shared__ char dsm[];
    __shared__ float s_b[256], s_g[256], s_be[256];
    __shared__ float s_sum[64][4], s_sq[64][4];
    __shared__ float s_mu[64], s_inv[64];
    __shared__ float s_cmax[2][256];

    __half* Xh = (__half*)dsm;               // 64 x 264 halfs (X, later H 256 cols)
    char* Wb = dsm + 64 * LDXH * 2;          // 3 x 16KB chunk buffers

    const int t = threadIdx.x, lane = t & 31, warp = t >> 5;
    const int gid = lane >> 2, tid4 = lane & 3;
    const int wr = warp >> 2, wc = warp & 3;
    const int pidx = wr * 32 + lane;         // index within the wc pair [0,64)
    const int p0 = blockIdx.x * 2, bB = p0 >> 12;

    // prologue: commit layer-1 chunk-0 AND chunk-1 slices (overlap X build)
    {
        uint32_t wbase = smem_u32(Wb) + wc * 4096;
        const float4* src0 = (const float4*)g_w1t + wc * 256;
#pragma unroll
        for (int u = 0; u < 4; u++) cp16(wbase + (pidx + u * 64) * 16, src0 + pidx + u * 64);
        asm volatile("cp.async.commit_group;" ::: "memory");
        const float4* src1 = (const float4*)g_w1t + 1024 + wc * 256;
#pragma unroll
        for (int u = 0; u < 4; u++)
            cp16(wbase + 16384 + (pidx + u * 64) * 16, src1 + pidx + u * 64);
        asm volatile("cp.async.commit_group;" ::: "memory");
    }
    s_b[t] = b1[t]; s_g[t] = g1[t]; s_be[t] = be1[t];

    // ---- build X[64 x 192] (fp16, row-major), 4 threads per row --------------
    {
        const int r = t >> 2, h = t & 3;
        const int p = p0 + (r >> 5);
        const int n = p & 4095;
        const int m = g_idx[(p << 5) + (r & 31)];
        const float* xm = xyz + ((size_t)(bB << 12) + m) * 3;
        const float* xn = xyz + ((size_t)(bB << 12) + n) * 3;
        float rel[3] = {xm[0] - xn[0], xm[1] - xn[1], xm[2] - xn[2]};
        __half* Xr = Xh + r * LDXH;
        const float4* pfr = (const float4*)(pf + ((size_t)(bB << 12) + m) * 64) + h * 4;
#pragma unroll
        for (int u = 0; u < 4; u++) {           // features: 16 cols each
            float4 f = __ldg(&pfr[u]);
            int c = h * 16 + u * 4;
            *(uint32_t*)(Xr + c)     = hpack(f.x, f.y);
            *(uint32_t*)(Xr + c + 2) = hpack(f.z, f.w);
        }
        if (h == 0) {
#pragma unroll
            for (int a = 0; a < 3; a++) Xr[64 + a] = __float2half_rn(rel[a]);
        } else if (h == 3) {
#pragma unroll
            for (int c = 187; c < 192; c++) Xr[c] = __float2half_rn(0.f);
        }
#pragma unroll
        for (int u = 0; u < 6; u++) {           // relative sin-emb: 6 each
            int j = h * 6 + u;
            int a = j >> 3, w8 = j & 7;
            float fr = expf((-logf(10000.0f) * (float)(w8 & 3)) / 3.0f);
            float ang = rel[a] * fr;
            float v = (w8 < 4) ? sinf(ang) : cosf(ang);
            Xr[67 + j] = __float2half_rn(v);
        }
        const float* ga = g_abs + (size_t)p * 96 + h * 24;   // absolute emb: 24 each
#pragma unroll
        for (int u = 0; u < 24; u++) Xr[91 + h * 24 + u] = __float2half_rn(ga[u]);
    }
    __syncthreads();

    // ---- layer 1 GEMM (6 chunks of 32 k-cols; cross-layer preload at tail) -----
    float4 acc[2][8];
#pragma unroll
    for (int nt = 0; nt < 8; nt++) {
        int c0 = wc * 64 + nt * 8 + 2 * tid4;
        float bx = s_b[c0], by = s_b[c0 + 1];
#pragma unroll
        for (int tile = 0; tile < 2; tile++) acc[tile][nt] = make_float4(bx, by, bx, by);
    }
    gemm_loop<6, true>(Xh, Wb, g_w1t, g_w2t, wr, wc, lane, pidx, acc);

    // ---- epilogue 1: LN stats -> GELU -> H (fp16, in place) --------------------
#pragma unroll
    for (int tile = 0; tile < 2; tile++) {
        float s0 = 0.f, q0 = 0.f, s1 = 0.f, q1 = 0.f;
#pragma unroll
        for (int nt = 0; nt < 8; nt++) {
            float4 c = acc[tile][nt];
            s0 += c.x + c.y; q0 += c.x * c.x + c.y * c.y;
            s1 += c.z + c.w; q1 += c.z * c.z + c.w * c.w;
        }
        s0 += __shfl_xor_sync(FULLMASK, s0, 1); s0 += __shfl_xor_sync(FULLMASK, s0, 2);
        q0 += __shfl_xor_sync(FULLMASK, q0, 1); q0 += __shfl_xor_sync(FULLMASK, q0, 2);
        s1 += __shfl_xor_sync(FULLMASK, s1, 1); s1 += __shfl_xor_sync(FULLMASK, s1, 2);
        q1 += __shfl_xor_sync(FULLMASK, q1, 1); q1 += __shfl_xor_sync(FULLMASK, q1, 2);
        if (tid4 == 0) {
            int r0 = wr * 32 + tile * 16 + gid;
            s_sum[r0][wc] = s0; s_sq[r0][wc] = q0;
            s_sum[r0 + 8][wc] = s1; s_sq[r0 + 8][wc] = q1;
        }
    }
    __syncthreads();
    if (t < 64) {
        float s = s_sum[t][0] + s_sum[t][1] + s_sum[t][2] + s_sum[t][3];
        float q = s_sq[t][0] + s_sq[t][1] + s_sq[t][2] + s_sq[t][3];
        float mu = s * (1.0f / 256.0f);
        s_mu[t] = mu;
        s_inv[t] = rsqrtf(fmaxf(q * (1.0f / 256.0f) - mu * mu, 0.f) + 1e-5f);
    }
    __syncthreads();
#pragma unroll
    for (int tile = 0; tile < 2; tile++) {
        int r0 = wr * 32 + tile * 16 + gid;
        float mu0 = s_mu[r0], inv0 = s_inv[r0], mu1 = s_mu[r0 + 8], inv1 = s_inv[r0 + 8];
#pragma unroll
        for (int nt = 0; nt < 8; nt++) {
            int c0 = wc * 64 + nt * 8 + 2 * tid4;
            float gg0 = s_g[c0], gg1 = s_g[c0 + 1], bb0 = s_be[c0], bb1 = s_be[c0 + 1];
            float4 c = acc[tile][nt];
            *(uint32_t*)(Xh + r0 * LDXH + c0) =
                hpack(gelu_exact((c.x - mu0) * inv0 * gg0 + bb0),
                      gelu_exact((c.y - mu0) * inv0 * gg1 + bb1));
            *(uint32_t*)(Xh + (r0 + 8) * LDXH + c0) =
                hpack(gelu_exact((c.z - mu1) * inv1 * gg0 + bb0),
                      gelu_exact((c.w - mu1) * inv1 * gg1 + bb1));
        }
    }
    __syncthreads();
    s_b[t] = b2[t]; s_g[t] = g2[t]; s_be[t] = be2[t];
    __syncthreads();

    // ---- layer 2 GEMM (A = H; 8 chunks; chunks 0,1 already in flight) ----------
#pragma unroll
    for (int nt = 0; nt < 8; nt++) {
        int c0 = wc * 64 + nt * 8 + 2 * tid4;
        float bx = s_b[c0], by = s_b[c0 + 1];
#pragma unroll
        for (int tile = 0; tile < 2; tile++) acc[tile][nt] = make_float4(bx, by, bx, by);
    }
    gemm_loop<8, false>(Xh, Wb, g_w2t, nullptr, wr, wc, lane, pidx, acc);

    // ---- epilogue 2: LN stats then LN + joint column max ------------------------
#pragma unroll
    for (int tile = 0; tile < 2; tile++) {
        float s0 = 0.f, q0 = 0.f, s1 = 0.f, q1 = 0.f;
#pragma unroll
        for (int nt = 0; nt < 8; nt++) {
            float4 c = acc[tile][nt];
            s0 += c.x + c.y; q0 += c.x * c.x + c.y * c.y;
            s1 += c.z + c.w; q1 += c.z * c.z + c.w * c.w;
        }
        s0 += __shfl_xor_sync(FULLMASK, s0, 1); s0 += __shfl_xor_sync(FULLMASK, s0, 2);
        q0 += __shfl_xor_sync(FULLMASK, q0, 1); q0 += __shfl_xor_sync(FULLMASK, q0, 2);
        s1 += __shfl_xor_sync(FULLMASK, s1, 1); s1 += __shfl_xor_sync(FULLMASK, s1, 2);
        q1 += __shfl_xor_sync(FULLMASK, q1, 1); q1 += __shfl_xor_sync(FULLMASK, q1, 2);
        if (tid4 == 0) {
            int r0 = wr * 32 + tile * 16 + gid;
            s_sum[r0][wc] = s0; s_sq[r0][wc] = q0;
            s_sum[r0 + 8][wc] = s1; s_sq[r0 + 8][wc] = q1;
        }
    }
    __syncthreads();
    if (t < 64) {
        float s = s_sum[t][0] + s_sum[t][1] + s_sum[t][2] + s_sum[t][3];
        float q = s_sq[t][0] + s_sq[t][1] + s_sq[t][2] + s_sq[t][3];
        float mu = s * (1.0f / 256.0f);
        s_mu[t] = mu;
        s_inv[t] = rsqrtf(fmaxf(q * (1.0f / 256.0f) - mu * mu, 0.f) + 1e-5f);
    }
    __syncthreads();
    {
        float m0[8], m1[8];
#pragma unroll
        for (int nt = 0; nt < 8; nt++) { m0[nt] = -INFINITY; m1[nt] = -INFINITY; }
#pragma unroll
        for (int tile = 0; tile < 2; tile++) {
            int r0 = wr * 32 + tile * 16 + gid;
            float mu0 = s_mu[r0], inv0 = s_inv[r0], mu1 = s_mu[r0 + 8], inv1 = s_inv[r0 + 8];
#pragma unroll
            for (int nt = 0; nt < 8; nt++) {
                int c0 = wc * 64 + nt * 8 + 2 * tid4;
                float gg0 = s_g[c0], gg1 = s_g[c0 + 1], bb0 = s_be[c0], bb1 = s_be[c0 + 1];
                float4 c = acc[tile][nt];
                float y00 = (c.x - mu0) * inv0 * gg0 + bb0;
                float y01 = (c.y - mu0) * inv0 * gg1 + bb1;
                float y10 = (c.z - mu1) * inv1 * gg0 + bb0;
                float y11 = (c.w - mu1) * inv1 * gg1 + bb1;
                m0[nt] = fmaxf(m0[nt], fmaxf(y00, y10));
                m1[nt] = fmaxf(m1[nt], fmaxf(y01, y11));
            }
        }
#pragma unroll
        for (int nt = 0; nt < 8; nt++) {
#pragma unroll
            for (int o = 4; o <= 16; o <<= 1) {
                m0[nt] = fmaxf(m0[nt], __shfl_xor_sync(FULLMASK, m0[nt], o));
                m1[nt] = fmaxf(m1[nt], __shfl_xor_sync(FULLMASK, m1[nt], o));
            }
            if (gid == 0) {
                int c0 = wc * 64 + nt * 8 + 2 * tid4;
                s_cmax[wr][c0] = m0[nt];
                s_cmax[wr][c0 + 1] = m1[nt];
            }
        }
    }
    __syncthreads();
    {
        float mm = fmaxf(s_cmax[0][t], s_cmax[1][t]);
        atomicMax(&g_pooled[(bB << 8) + t], fkey(mm));
    }
}

// ==================== final 4-row MLP (k-sliced, 4 tiny kernels) =============
__device__ __forceinline__ float bsum256(float v, float* sred) {
#pragma unroll
    for (int o = 16; o; o >>= 1) v += __shfl_xor_sync(FULLMASK, v, o);
    if ((threadIdx.x & 31) == 0) sred[threadIdx.x >> 5] = v;
    __syncthreads();
    float s = 0.f;
#pragma unroll
    for (int w = 0; w < 8; w++) s += sred[w];
    __syncthreads();
    return s;
}

__global__ __launch_bounds__(256) void k_fg(const float* __restrict__ w, int stage) {
    __shared__ float xin[4][256];
    int j = blockIdx.x, t = threadIdx.x;
    if (stage == 0)
        for (int i = t; i < 1024; i += 256) ((float*)xin)[i] = funkey(g_pooled[i]);
    else
        for (int i = t; i < 1024; i += 256) ((float*)xin)[i] = g_ft[i];
    __syncthreads();
    float a0 = 0.f, a1 = 0.f, a2 = 0.f, a3 = 0.f;
#pragma unroll
    for (int kk = 0; kk < 16; kk++) {
        float wv = __ldg(&w[(j * 16 + kk) * 256 + t]);
        a0 = fmaf(xin[0][j * 16 + kk], wv, a0);
        a1 = fmaf(xin[1][j * 16 + kk], wv, a1);
        a2 = fmaf(xin[2][j * 16 + kk], wv, a2);
        a3 = fmaf(xin[3][j * 16 + kk], wv, a3);
    }
    float* dst = stage ? g_fp2 : g_fp1;
    dst[(j * 4 + 0) * 256 + t] = a0;
    dst[(j * 4 + 1) * 256 + t] = a1;
    dst[(j * 4 + 2) * 256 + t] = a2;
    dst[(j * 4 + 3) * 256 + t] = a3;
}

__global__ __launch_bounds__(256) void k_fr(const float* __restrict__ bias,
                                            const float* __restrict__ gam,
                                            const float* __restrict__ bet,
                                            int stage, float* __restrict__ out) {
    __shared__ float sred[8];
    int t = threadIdx.x;
    const float* src = stage ? g_fp2 : g_fp1;
    for (int b = 0; b < 4; b++) {
        float y = bias[t];
#pragma unroll
        for (int j = 0; j < 16; j++) y += src[(j * 4 + b) * 256 + t];
        float mu = bsum256(y, sred) * (1.0f / 256.0f);
        float d = y - mu;
        float var = bsum256(d * d, sred) * (1.0f / 256.0f);
        float z = d * rsqrtf(var + 1e-5f) * gam[t] + bet[t];
        if (stage == 0) g_ft[b * 256 + t] = gelu_exact(z);
        else out[b * 256 + t] = z;
    }
}

// ==================== launcher ===============================================
extern "C" void kernel_launch(void* const* d_in, const int* in_sizes, int n_in,
                              void* d_out, int out_size) {
    const float* xyz  = (const float*)d_in[0];
    const float* pf   = (const float*)d_in[1];
    const float* w1   = (const float*)d_in[2];
    const float* b1   = (const float*)d_in[3];
    const float* g1   = (const float*)d_in[4];
    const float* be1  = (const float*)d_in[5];
    const float* w2   = (const float*)d_in[6];
    const float* b2   = (const float*)d_in[7];
    const float* g2   = (const float*)d_in[8];
    const float* be2  = (const float*)d_in[9];
    const float* pw1  = (const float*)d_in[10];
    const float* pb1  = (const float*)d_in[11];
    const float* pg1  = (const float*)d_in[12];
    const float* pbe1 = (const float*)d_in[13];
    const float* pw2  = (const float*)d_in[14];
    const float* pb2  = (const float*)d_in[15];
    const float* pg2  = (const float*)d_in[16];
    const float* pbe2 = (const float*)d_in[17];
    float* out = (float*)d_out;

    static int attr_done = 0;
    if (!attr_done) {
        cudaFuncSetAttribute(k_mlp, cudaFuncAttributeMaxDynamicSharedMemorySize, SMEM_DYN);
        attr_done = 1;
    }

    k_init<<<4, 256>>>();
    k_prep<<<112, 256>>>(w1, w2);
    k_ball<<<dim3(512, 4), 256>>>(xyz);
    k_mlp<<<8192, 256, SMEM_DYN>>>(xyz, pf, b1, g1, be1, b2, g2, be2);
    k_fg<<<16, 256>>>(pw1, 0);
    k_fr<<<1, 256>>>(pb1, pg1, pbe1, 0, out);
    k_fg<<<16, 256>>>(pw2, 1);
    k_fr<<<1, 256>>>(pb2, pg2, pbe2, 1, out);
}

// round 17
// speedup vs baseline: 1.0519x; 1.0519x over previous
#include <cuda_runtime.h>
#include <cuda_fp16.h>
#include <cstdint>
#include <math.h>

#define FULLMASK 0xffffffffu
#define LDXH 264   // X/H row stride (halfs) >= 256; word-stride 132 % 32 == 4 -> conflict-free

// ==================== device scratch (no allocations allowed) ===============
__device__ int      g_idx[4 * 4096 * 32];
__device__ float    g_abs[4 * 4096 * 96];
__device__ unsigned g_pooled[4 * 256];
__device__ float4   g_w1t[6 * 1024];     // 6 chunks x 16KB ldmatrix-tile images
__device__ float4   g_w2t[8 * 1024];     // 8 chunks x 16KB
__device__ float    g_fp1[16 * 1024], g_fp2[16 * 1024], g_ft[1024];

// ==================== helpers ===============================================
__device__ __forceinline__ uint32_t smem_u32(const void* p) {
    uint32_t a;
    asm("{ .reg .u64 t; cvta.to.shared.u64 t, %1; cvt.u32.u64 %0, t; }" : "=r"(a) : "l"(p));
    return a;
}
__device__ __forceinline__ uint16_t h16(float x) {
    uint16_t u;
    asm("cvt.rn.f16.f32 %0, %1;" : "=h"(u) : "f"(x));
    return u;
}
__device__ __forceinline__ uint32_t hpack(float a, float b) {
    return (uint32_t)h16(a) | ((uint32_t)h16(b) << 16);
}
__device__ __forceinline__ unsigned fkey(float f) {
    int i = __float_as_int(f);
    return (i >= 0) ? ((unsigned)i | 0x80000000u) : ~(unsigned)i;
}
__device__ __forceinline__ float funkey(unsigned u) {
    int i = (u & 0x80000000u) ? (int)(u & 0x7fffffffu) : (int)(~u);
    return __int_as_float(i);
}
__device__ __forceinline__ float gelu_exact(float x) {
    return 0.5f * x * (1.0f + erff(x * 0.70710678118654752f));
}
// m16n8k16 fp16 warp MMA, fp32 accumulate (family-portable sm_80+)
__device__ __forceinline__ void mma16(float4& d, uint32_t a0, uint32_t a1,
                                      uint32_t a2, uint32_t a3, uint32_t b0, uint32_t b1) {
    asm volatile("mma.sync.aligned.m16n8k16.row.col.f32.f16.f16.f32 "
                 "{%0,%1,%2,%3}, {%4,%5,%6,%7}, {%8,%9}, {%0,%1,%2,%3};"
                 : "+f"(d.x), "+f"(d.y), "+f"(d.z), "+f"(d.w)
                 : "r"(a0), "r"(a1), "r"(a2), "r"(a3), "r"(b0), "r"(b1));
}
__device__ __forceinline__ void ldm_x4(uint32_t& r0, uint32_t& r1, uint32_t& r2,
                                       uint32_t& r3, uint32_t addr) {
    asm volatile("ldmatrix.sync.aligned.m8n8.x4.shared.b16 {%0,%1,%2,%3}, [%4];"
                 : "=r"(r0), "=r"(r1), "=r"(r2), "=r"(r3) : "r"(addr));
}
__device__ __forceinline__ void cp16(uint32_t sdst, const void* gsrc) {
    asm volatile("cp.async.cg.shared.global [%0], [%1], 16;" :: "r"(sdst), "l"(gsrc));
}
__device__ __forceinline__ void bar_pair(int id) {
    asm volatile("bar.sync %0, 64;" :: "r"(id) : "memory");
}

// ==================== kernel P: ldmatrix-tile weight images + pooled init ===
// chunk(16KB) = 4 wc-slices of 4KB = 256 rows of 16B.
// row id within chunk: wc(2) | ks(1) | p(2) | m(2) | rr(3)
//   nt = 2p + (m>>1); kb = c*32 + ks*16 + (m&1)*8; n = wc*64 + nt*8 + rr
//   row halfs hh=0..7: W[kb+hh][n]  (ldmatrix m8n8: lane L <- row L>>2, word L&3
//   => b0 lane L = {W[kb+2(L&3)][n(L>>2)], W[kb+2(L&3)+1][n]} — identical to R15 fragments)
__global__ __launch_bounds__(256) void k_prep(const float* __restrict__ w1,
                                              const float* __restrict__ w2) {
    if (blockIdx.x == 56) {                      // pooled-max init
        for (int i = threadIdx.x; i < 1024; i += 256) g_pooled[i] = 0x007FFFFFu;
        return;
    }
    int id = blockIdx.x * 256 + threadIdx.x;
    const float* w;
    uint4* dst;
    int c, rem;
    if (id < 6144) {                             // layer 1: 6 chunks
        w = w1; dst = (uint4*)g_w1t;
        c = id >> 10; rem = id & 1023;
    } else {                                     // layer 2: 8 chunks
        id -= 6144;
        w = w2; dst = (uint4*)g_w2t;
        c = id >> 10; rem = id & 1023;
    }
    int wc = rem >> 8, ks = (rem >> 7) & 1, p = (rem >> 5) & 3, m = (rem >> 3) & 3, rr = rem & 7;
    int nt = 2 * p + (m >> 1);
    int kb = c * 32 + ks * 16 + (m & 1) * 8;
    int n = wc * 64 + nt * 8 + rr;
    bool l1 = (w == w1);
    float v[8];
#pragma unroll
    for (int hh = 0; hh < 8; hh++) {
        int k = kb + hh;
        v[hh] = (!l1 || k < 187) ? w[k * 256 + n] : 0.f;
    }
    dst[c * 1024 + rem] = make_uint4(hpack(v[0], v[1]), hpack(v[2], v[3]),
                                     hpack(v[4], v[5]), hpack(v[6], v[7]));
}

// ==================== kernel 1: ball query + absolute emb (validated) =======
__global__ __launch_bounds__(256) void k_ball(const float* __restrict__ xyz) {
    __shared__ float sx[4096], sy[4096], sz[4096];
    const int b = blockIdx.y;
    const float* base = xyz + (size_t)b * 4096 * 3;
    for (int i = threadIdx.x; i < 4096; i += 256) {
        float3 v = *(const float3*)(base + 3 * i);
        sx[i] = v.x; sy[i] = v.y; sz[i] = v.z;
    }
    __syncthreads();
    const int lane = threadIdx.x & 31, warp = threadIdx.x >> 5;
    const int n = blockIdx.x * 8 + warp;
    const float qx = sx[n], qy = sy[n], qz = sz[n];
    const int p = (b << 12) + n;
    int cnt = 0, fm = n;
    for (int c = 0; c < 128; c++) {
        int m = c * 32 + lane;
        float dx = sx[m] - qx, dy = sy[m] - qy, dz = sz[m] - qz;
        float sq = __fadd_rn(__fadd_rn(__fmul_rn(dx, dx), __fmul_rn(dy, dy)), __fmul_rn(dz, dz));
        bool in = (sq <= 0.0256f);
        unsigned mask = __ballot_sync(FULLMASK, in);
        if (mask) {
            if (cnt == 0) fm = c * 32 + (__ffs(mask) - 1);
            if (in) {
                int pos = cnt + __popc(mask & ((1u << lane) - 1u));
                if (pos < 32) g_idx[p * 32 + pos] = m;
            }
            cnt += __popc(mask);
            if (cnt >= 32) break;
        }
    }
    for (int k = cnt + lane; k < 32; k += 32) g_idx[p * 32 + k] = fm;
    int jj = lane & 15;
    float fr = expf((-logf(10000.0f) * (float)jj) / 15.0f);
    float co[3] = {qx, qy, qz};
#pragma unroll
    for (int a = 0; a < 3; a++) {
        float ang = co[a] * fr;
        g_abs[(size_t)p * 96 + a * 32 + lane] = (lane >= 16) ? cosf(ang) : sinf(ang);
    }
}

// ==================== kernel 2: fp16 mma.sync fused MLP + joint max =========
// CTA: 64 rows x 256 cols; 256 threads, 8 warps in 2(M) x 4(N) grid.
// 2 CTAs/SM; per-wc-pair slices + named barriers; ldmatrix fragment loads.
#define SMEM_DYN (64 * LDXH * 2 + 2 * 16384)

// fully-unrolled double-buffered 32-kcol-chunk GEMM (ldmatrix fragments).
// Chunk-0 slice must already be committed when called.
template <int NCH, bool PRELOAD>
__device__ __forceinline__ void gemm_loop(uint32_t aaddr,
                                          char* Wb, const float4* gw,
                                          const float4* next_gw,
                                          int wc, int lane, int pidx,
                                          float4 acc[2][8]) {
    const uint32_t w0a = smem_u32(Wb) + wc * 4096;
    const uint32_t w1a = w0a + 16384;
    const uint32_t bl = (uint32_t)(((lane >> 3) * 128) + ((lane & 7) * 16));
#pragma unroll
    for (int i = 0; i < NCH; i++) {
        asm volatile("cp.async.wait_group 0;" ::: "memory");
        bar_pair(wc + 1);
        if (i + 1 < NCH) {                     // prefetch own slice of next chunk
            uint32_t dst = (i & 1) ? w0a : w1a;
            const float4* src = gw + (i + 1) * 1024 + wc * 256;
#pragma unroll
            for (int u = 0; u < 4; u++) cp16(dst + (pidx + u * 64) * 16, src + pidx + u * 64);
            asm volatile("cp.async.commit_group;" ::: "memory");
        } else if (PRELOAD) {                  // tail: preload next image chunk 0
            uint32_t dst = (i & 1) ? w0a : w1a;
            const float4* src = next_gw + wc * 256;
#pragma unroll
            for (int u = 0; u < 4; u++) cp16(dst + (pidx + u * 64) * 16, src + pidx + u * 64);
            asm volatile("cp.async.commit_group;" ::: "memory");
        }
        const uint32_t bba = ((i & 1) ? w1a : w0a) + bl;
#pragma unroll
        for (int ks = 0; ks < 2; ks++) {
            const int ko = i * 64 + ks * 32;       // A byte offset (compile-time)
            uint32_t a0[4], a1[4];
            ldm_x4(a0[0], a0[1], a0[2], a0[3], aaddr + ko);                    // tile 0
            ldm_x4(a1[0], a1[1], a1[2], a1[3], aaddr + 16 * LDXH * 2 + ko);    // tile 1
#pragma unroll
            for (int p = 0; p < 4; p++) {
                uint32_t b0, b1, b2, b3;
                ldm_x4(b0, b1, b2, b3, bba + ks * 2048 + p * 512);
                mma16(acc[0][2 * p],     a0[0], a0[1], a0[2], a0[3], b0, b1);
                mma16(acc[0][2 * p + 1], a0[0], a0[1], a0[2], a0[3], b2, b3);
                mma16(acc[1][2 * p],     a1[0], a1[1], a1[2], a1[3], b0, b1);
                mma16(acc[1][2 * p + 1], a1[0], a1[1], a1[2], a1[3], b2, b3);
            }
        }
    }
    __syncthreads();
}

__global__ __launch_bounds__(256, 2) void k_mlp(
    const float* __restrict__ xyz, const float* __restrict__ pf,
    const float* __restrict__ b1, const float* __restrict__ g1, const float* __restrict__ be1,
    const float* __restrict__ b2, const float* __restrict__ g2, const float* __restrict__ be2) {
    extern __shared__ char dsm[];
    __shared__ float s_b[256], s_g[256], s_be[256];
    __shared__ float s_sum[64][4], s_sq[64][4];
    __shared__ float s_mu[64], s_inv[64];
    __shared__ float s_cmax[2][256];

    __half* Xh = (__half*)dsm;               // 64 x 264 halfs (X, later H 256 cols)
    char* Wb = dsm + 64 * LDXH * 2;          // 2 x 16KB chunk buffers

    const int t = threadIdx.x, lane = t & 31, warp = t >> 5;
    const int gid = lane >> 2, tid4 = lane & 3;
    const int wr = warp >> 2, wc = warp & 3;
    const int pidx = wr * 32 + lane;         // index within the wc pair [0,64)
    const int p0 = blockIdx.x * 2, bB = p0 >> 12;

    // early per-pair preload of layer-1 chunk-0 slice (overlaps X build)
    {
        uint32_t w0a = smem_u32(Wb) + wc * 4096;
        const float4* src = (const float4*)g_w1t + wc * 256;
#pragma unroll
        for (int u = 0; u < 4; u++) cp16(w0a + (pidx + u * 64) * 16, src + pidx + u * 64);
        asm volatile("cp.async.commit_group;" ::: "memory");
    }
    s_b[t] = b1[t]; s_g[t] = g1[t]; s_be[t] = be1[t];

    // ---- build X[64 x 192] (fp16, row-major), 4 threads per row --------------
    {
        const int r = t >> 2, h = t & 3;
        const int p = p0 + (r >> 5);
        const int n = p & 4095;
        const int m = g_idx[(p << 5) + (r & 31)];
        const float* xm = xyz + ((size_t)(bB << 12) + m) * 3;
        const float* xn = xyz + ((size_t)(bB << 12) + n) * 3;
        float rel[3] = {xm[0] - xn[0], xm[1] - xn[1], xm[2] - xn[2]};
        __half* Xr = Xh + r * LDXH;
        const float4* pfr = (const float4*)(pf + ((size_t)(bB << 12) + m) * 64) + h * 4;
#pragma unroll
        for (int u = 0; u < 4; u++) {           // features: 16 cols each
            float4 f = __ldg(&pfr[u]);
            int c = h * 16 + u * 4;
            *(uint32_t*)(Xr + c)     = hpack(f.x, f.y);
            *(uint32_t*)(Xr + c + 2) = hpack(f.z, f.w);
        }
        if (h == 0) {
#pragma unroll
            for (int a = 0; a < 3; a++) Xr[64 + a] = __float2half_rn(rel[a]);
        } else if (h == 3) {
#pragma unroll
            for (int c = 187; c < 192; c++) Xr[c] = __float2half_rn(0.f);
        }
#pragma unroll
        for (int u = 0; u < 6; u++) {           // relative sin-emb: 6 each
            int j = h * 6 + u;
            int a = j >> 3, w8 = j & 7;
            float fr = expf((-logf(10000.0f) * (float)(w8 & 3)) / 3.0f);
            float ang = rel[a] * fr;
            float v = (w8 < 4) ? sinf(ang) : cosf(ang);
            Xr[67 + j] = __float2half_rn(v);
        }
        const float* ga = g_abs + (size_t)p * 96 + h * 24;   // absolute emb: 24 each
#pragma unroll
        for (int u = 0; u < 24; u++) Xr[91 + h * 24 + u] = __float2half_rn(ga[u]);
    }
    __syncthreads();

    // ldmatrix A lane address (row-major X): matrix0 rows wr*32.., m1 +8, m2 k+8, m3 both
    const uint32_t aaddr = smem_u32(Xh) +
        (uint32_t)(((wr * 32 + ((lane >> 3) & 1) * 8 + (lane & 7)) * LDXH + (lane >> 4) * 8) * 2);

    // ---- layer 1 GEMM (6 chunks of 32 k-cols; cross-layer preload at tail) -----
    float4 acc[2][8];
#pragma unroll
    for (int nt = 0; nt < 8; nt++) {
        int c0 = wc * 64 + nt * 8 + 2 * tid4;
        float bx = s_b[c0], by = s_b[c0 + 1];
#pragma unroll
        for (int tile = 0; tile < 2; tile++) acc[tile][nt] = make_float4(bx, by, bx, by);
    }
    gemm_loop<6, true>(aaddr, Wb, g_w1t, g_w2t, wc, lane, pidx, acc);

    // ---- epilogue 1: LN stats -> GELU -> H (fp16, in place) --------------------
#pragma unroll
    for (int tile = 0; tile < 2; tile++) {
        float s0 = 0.f, q0 = 0.f, s1 = 0.f, q1 = 0.f;
#pragma unroll
        for (int nt = 0; nt < 8; nt++) {
            float4 c = acc[tile][nt];
            s0 += c.x + c.y; q0 += c.x * c.x + c.y * c.y;
            s1 += c.z + c.w; q1 += c.z * c.z + c.w * c.w;
        }
        s0 += __shfl_xor_sync(FULLMASK, s0, 1); s0 += __shfl_xor_sync(FULLMASK, s0, 2);
        q0 += __shfl_xor_sync(FULLMASK, q0, 1); q0 += __shfl_xor_sync(FULLMASK, q0, 2);
        s1 += __shfl_xor_sync(FULLMASK, s1, 1); s1 += __shfl_xor_sync(FULLMASK, s1, 2);
        q1 += __shfl_xor_sync(FULLMASK, q1, 1); q1 += __shfl_xor_sync(FULLMASK, q1, 2);
        if (tid4 == 0) {
            int r0 = wr * 32 + tile * 16 + gid;
            s_sum[r0][wc] = s0; s_sq[r0][wc] = q0;
            s_sum[r0 + 8][wc] = s1; s_sq[r0 + 8][wc] = q1;
        }
    }
    __syncthreads();
    if (t < 64) {
        float s = s_sum[t][0] + s_sum[t][1] + s_sum[t][2] + s_sum[t][3];
        float q = s_sq[t][0] + s_sq[t][1] + s_sq[t][2] + s_sq[t][3];
        float mu = s * (1.0f / 256.0f);
        s_mu[t] = mu;
        s_inv[t] = rsqrtf(fmaxf(q * (1.0f / 256.0f) - mu * mu, 0.f) + 1e-5f);
    }
    __syncthreads();
#pragma unroll
    for (int tile = 0; tile < 2; tile++) {
        int r0 = wr * 32 + tile * 16 + gid;
        float mu0 = s_mu[r0], inv0 = s_inv[r0], mu1 = s_mu[r0 + 8], inv1 = s_inv[r0 + 8];
#pragma unroll
        for (int nt = 0; nt < 8; nt++) {
            int c0 = wc * 64 + nt * 8 + 2 * tid4;
            float gg0 = s_g[c0], gg1 = s_g[c0 + 1], bb0 = s_be[c0], bb1 = s_be[c0 + 1];
            float4 c = acc[tile][nt];
            *(uint32_t*)(Xh + r0 * LDXH + c0) =
                hpack(gelu_exact((c.x - mu0) * inv0 * gg0 + bb0),
                      gelu_exact((c.y - mu0) * inv0 * gg1 + bb1));
            *(uint32_t*)(Xh + (r0 + 8) * LDXH + c0) =
                hpack(gelu_exact((c.z - mu1) * inv1 * gg0 + bb0),
                      gelu_exact((c.w - mu1) * inv1 * gg1 + bb1));
        }
    }
    __syncthreads();
    s_b[t] = b2[t]; s_g[t] = g2[t]; s_be[t] = be2[t];
    __syncthreads();

    // ---- layer 2 GEMM (A = H; 8 chunks; chunk-0 slice preloaded at L1 tail) ----
#pragma unroll
    for (int nt = 0; nt < 8; nt++) {
        int c0 = wc * 64 + nt * 8 + 2 * tid4;
        float bx = s_b[c0], by = s_b[c0 + 1];
#pragma unroll
        for (int tile = 0; tile < 2; tile++) acc[tile][nt] = make_float4(bx, by, bx, by);
    }
    gemm_loop<8, false>(aaddr, Wb, g_w2t, nullptr, wc, lane, pidx, acc);

    // ---- epilogue 2: LN stats then LN + joint column max ------------------------
#pragma unroll
    for (int tile = 0; tile < 2; tile++) {
        float s0 = 0.f, q0 = 0.f, s1 = 0.f, q1 = 0.f;
#pragma unroll
        for (int nt = 0; nt < 8; nt++) {
            float4 c = acc[tile][nt];
            s0 += c.x + c.y; q0 += c.x * c.x + c.y * c.y;
            s1 += c.z + c.w; q1 += c.z * c.z + c.w * c.w;
        }
        s0 += __shfl_xor_sync(FULLMASK, s0, 1); s0 += __shfl_xor_sync(FULLMASK, s0, 2);
        q0 += __shfl_xor_sync(FULLMASK, q0, 1); q0 += __shfl_xor_sync(FULLMASK, q0, 2);
        s1 += __shfl_xor_sync(FULLMASK, s1, 1); s1 += __shfl_xor_sync(FULLMASK, s1, 2);
        q1 += __shfl_xor_sync(FULLMASK, q1, 1); q1 += __shfl_xor_sync(FULLMASK, q1, 2);
        if (tid4 == 0) {
            int r0 = wr * 32 + tile * 16 + gid;
            s_sum[r0][wc] = s0; s_sq[r0][wc] = q0;
            s_sum[r0 + 8][wc] = s1; s_sq[r0 + 8][wc] = q1;
        }
    }
    __syncthreads();
    if (t < 64) {
        float s = s_sum[t][0] + s_sum[t][1] + s_sum[t][2] + s_sum[t][3];
        float q = s_sq[t][0] + s_sq[t][1] + s_sq[t][2] + s_sq[t][3];
        float mu = s * (1.0f / 256.0f);
        s_mu[t] = mu;
        s_inv[t] = rsqrtf(fmaxf(q * (1.0f / 256.0f) - mu * mu, 0.f) + 1e-5f);
    }
    __syncthreads();
    {
        float m0[8], m1[8];
#pragma unroll
        for (int nt = 0; nt < 8; nt++) { m0[nt] = -INFINITY; m1[nt] = -INFINITY; }
#pragma unroll
        for (int tile = 0; tile < 2; tile++) {
            int r0 = wr * 32 + tile * 16 + gid;
            float mu0 = s_mu[r0], inv0 = s_inv[r0], mu1 = s_mu[r0 + 8], inv1 = s_inv[r0 + 8];
#pragma unroll
            for (int nt = 0; nt < 8; nt++) {
                int c0 = wc * 64 + nt * 8 + 2 * tid4;
                float gg0 = s_g[c0], gg1 = s_g[c0 + 1], bb0 = s_be[c0], bb1 = s_be[c0 + 1];
                float4 c = acc[tile][nt];
                float y00 = (c.x - mu0) * inv0 * gg0 + bb0;
                float y01 = (c.y - mu0) * inv0 * gg1 + bb1;
                float y10 = (c.z - mu1) * inv1 * gg0 + bb0;
                float y11 = (c.w - mu1) * inv1 * gg1 + bb1;
                m0[nt] = fmaxf(m0[nt], fmaxf(y00, y10));
                m1[nt] = fmaxf(m1[nt], fmaxf(y01, y11));
            }
        }
#pragma unroll
        for (int nt = 0; nt < 8; nt++) {
#pragma unroll
            for (int o = 4; o <= 16; o <<= 1) {
                m0[nt] = fmaxf(m0[nt], __shfl_xor_sync(FULLMASK, m0[nt], o));
                m1[nt] = fmaxf(m1[nt], __shfl_xor_sync(FULLMASK, m1[nt], o));
            }
            if (gid == 0) {
                int c0 = wc * 64 + nt * 8 + 2 * tid4;
                s_cmax[wr][c0] = m0[nt];
                s_cmax[wr][c0 + 1] = m1[nt];
            }
        }
    }
    __syncthreads();
    {
        float mm = fmaxf(s_cmax[0][t], s_cmax[1][t]);
        atomicMax(&g_pooled[(bB << 8) + t], fkey(mm));
    }
}

// ==================== final 4-row MLP (k-sliced, 4 tiny kernels) =============
__device__ __forceinline__ float bsum256(float v, float* sred) {
#pragma unroll
    for (int o = 16; o; o >>= 1) v += __shfl_xor_sync(FULLMASK, v, o);
    if ((threadIdx.x & 31) == 0) sred[threadIdx.x >> 5] = v;
    __syncthreads();
    float s = 0.f;
#pragma unroll
    for (int w = 0; w < 8; w++) s += sred[w];
    __syncthreads();
    return s;
}

__global__ __launch_bounds__(256) void k_fg(const float* __restrict__ w, int stage) {
    __shared__ float xin[4][256];
    int j = blockIdx.x, t = threadIdx.x;
    if (stage == 0)
        for (int i = t; i < 1024; i += 256) ((float*)xin)[i] = funkey(g_pooled[i]);
    else
        for (int i = t; i < 1024; i += 256) ((float*)xin)[i] = g_ft[i];
    __syncthreads();
    float a0 = 0.f, a1 = 0.f, a2 = 0.f, a3 = 0.f;
#pragma unroll
    for (int kk = 0; kk < 16; kk++) {
        float wv = __ldg(&w[(j * 16 + kk) * 256 + t]);
        a0 = fmaf(xin[0][j * 16 + kk], wv, a0);
        a1 = fmaf(xin[1][j * 16 + kk], wv, a1);
        a2 = fmaf(xin[2][j * 16 + kk], wv, a2);
        a3 = fmaf(xin[3][j * 16 + kk], wv, a3);
    }
    float* dst = stage ? g_fp2 : g_fp1;
    dst[(j * 4 + 0) * 256 + t] = a0;
    dst[(j * 4 + 1) * 256 + t] = a1;
    dst[(j * 4 + 2) * 256 + t] = a2;
    dst[(j * 4 + 3) * 256 + t] = a3;
}

__global__ __launch_bounds__(256) void k_fr(const float* __restrict__ bias,
                                            const float* __restrict__ gam,
                                            const float* __restrict__ bet,
                                            int stage, float* __restrict__ out) {
    __shared__ float sred[8];
    int t = threadIdx.x;
    const float* src = stage ? g_fp2 : g_fp1;
    for (int b = 0; b < 4; b++) {
        float y = bias[t];
#pragma unroll
        for (int j = 0; j < 16; j++) y += src[(j * 4 + b) * 256 + t];
        float mu = bsum256(y, sred) * (1.0f / 256.0f);
        float d = y - mu;
        float var = bsum256(d * d, sred) * (1.0f / 256.0f);
        float z = d * rsqrtf(var + 1e-5f) * gam[t] + bet[t];
        if (stage == 0) g_ft[b * 256 + t] = gelu_exact(z);
        else out[b * 256 + t] = z;
    }
}

// ==================== launcher ===============================================
extern "C" void kernel_launch(void* const* d_in, const int* in_sizes, int n_in,
                              void* d_out, int out_size) {
    const float* xyz  = (const float*)d_in[0];
    const float* pf   = (const float*)d_in[1];
    const float* w1   = (const float*)d_in[2];
    const float* b1   = (const float*)d_in[3];
    const float* g1   = (const float*)d_in[4];
    const float* be1  = (const float*)d_in[5];
    const float* w2   = (const float*)d_in[6];
    const float* b2   = (const float*)d_in[7];
    const float* g2   = (const float*)d_in[8];
    const float* be2  = (const float*)d_in[9];
    const float* pw1  = (const float*)d_in[10];
    const float* pb1  = (const float*)d_in[11];
    const float* pg1  = (const float*)d_in[12];
    const float* pbe1 = (const float*)d_in[13];
    const float* pw2  = (const float*)d_in[14];
    const float* pb2  = (const float*)d_in[15];
    const float* pg2  = (const float*)d_in[16];
    const float* pbe2 = (const float*)d_in[17];
    float* out = (float*)d_out;

    static int attr_done = 0;
    if (!attr_done) {
        cudaFuncSetAttribute(k_mlp, cudaFuncAttributeMaxDynamicSharedMemorySize, SMEM_DYN);
        attr_done = 1;
    }

    k_prep<<<57, 256>>>(w1, w2);
    k_ball<<<dim3(512, 4), 256>>>(xyz);
    k_mlp<<<8192, 256, SMEM_DYN>>>(xyz, pf, b1, g1, be1, b2, g2, be2);
    k_fg<<<16, 256>>>(pw1, 0);
    k_fr<<<1, 256>>>(pb1, pg1, pbe1, 0, out);
    k_fg<<<16, 256>>>(pw2, 1);
    k_fr<<<1, 256>>>(pb2, pg2, pbe2, 1, out);
}